// round 17
// baseline (speedup 1.0000x reference)
#include <cuda_runtime.h>
#include <math.h>

#define B_   4
#define C_   256
#define CO_  256
#define NTOT 85          // 64 (g=8) + 16 (g=4) + 4 (g=2) + 1 (g=1)
#define L3B  0
#define L2B  64
#define L1B  80
#define L0B  84
#define ROWS 32          // 1 + 4 + 8 + 19 kept rows per batch

// Output offsets (floats): (out, sparse_seq, all_coords, sparsity)
#define OFS_SPARSE   67108864ull
#define OFS_COORDS   (67108864ull + 32768ull)
#define OFS_SPARSITY (67108864ull + 32768ull + 512ull)

#define NEG_INF __int_as_float(0xff800000)

// Scratch (device globals — allocations forbidden).
__device__ float g_pyr[B_][64][C_];     // level-3 pyramid, cell-major
__device__ float g_kfn[B_][ROWS][C_];   // LayerNormed kept rows
__device__ float g_wT[CO_][C_];         // transposed weight: g_wT[d][c] = w[c][d]
__device__ int   g_map8[B_][64];        // finest-kept row per 8x8 fine cell

// ---------------------------------------------------------------------------
// K1: grid max pool (blocks 0..8191) + w transpose (blocks 8192..8255).
// Transpose blocks' scattered stores hide under pool's DRAM-bound phase.
// ---------------------------------------------------------------------------
__global__ void __launch_bounds__(256, 8)
k_pool(const float* __restrict__ x, const float* __restrict__ wmat) {
    int t = threadIdx.x;

    if (blockIdx.x >= 8192) {
        int base = (blockIdx.x - 8192) * 1024 + t * 4;
        float4 v = *reinterpret_cast<const float4*>(wmat + base);
        int c = base >> 8;
        int d = base & 255;
        g_wT[d + 0][c] = v.x;
        g_wT[d + 1][c] = v.y;
        g_wT[d + 2][c] = v.z;
        g_wT[d + 3][c] = v.w;
        return;
    }

    int gy = blockIdx.x & 7;
    int bc = blockIdx.x >> 3;
    int c  = bc & 255;
    int b  = bc >> 8;

    int lane = t & 31;
    int gx   = t >> 5;

    const float4* base4 = reinterpret_cast<const float4*>(
        x + ((size_t)(b * 256 + c) * 256 + (size_t)gy * 32) * 256) + gx * 8;
    int r0 = lane >> 3;
    int f4 = lane & 7;

    float m = NEG_INF;
    #pragma unroll
    for (int i = 0; i < 8; i++) {
        float4 v = __ldcs(base4 + (size_t)(i * 4 + r0) * 64 + f4);
        m = fmaxf(m, fmaxf(fmaxf(v.x, v.y), fmaxf(v.z, v.w)));
    }
    #pragma unroll
    for (int o = 16; o > 0; o >>= 1)
        m = fmaxf(m, __shfl_xor_sync(0xffffffffu, m, o));
    if (lane == 0) g_pyr[b][gy * 8 + gx][c] = m;
}

// ---------------------------------------------------------------------------
// K2: prep — pyramid upper levels + L2 norms + rank-based top-k + coords +
// cell->row map + LayerNorm of the 32 kept rows -> g_kfn. One block/batch.
// ---------------------------------------------------------------------------
__global__ void k_prep(const float* __restrict__ ln_g, const float* __restrict__ ln_b,
                       float* __restrict__ dout) {
    int b = blockIdx.x;
    int t = threadIdx.x;
    int lane = t & 31, w = t >> 5;

    __shared__ float s_up[21][C_];
    __shared__ float sl2[NTOT];
    __shared__ float simp2[16], simp1[4];
    __shared__ int   ssel[ROWS];
    __shared__ int   srank3[64], srank2[16], srank1[4];

    // --- phase A: upper pyramid levels into smem ---
    float v2a[16];
    #pragma unroll
    for (int u = 0; u < 16; u++) {
        int gy = u >> 2, gx = u & 3;
        int c0 = (gy * 2) * 8 + gx * 2;
        float v = fmaxf(fmaxf(g_pyr[b][c0][t],     g_pyr[b][c0 + 1][t]),
                        fmaxf(g_pyr[b][c0 + 8][t], g_pyr[b][c0 + 9][t]));
        v2a[u] = v;
        s_up[u][t] = v;
    }
    float v1a[4];
    #pragma unroll
    for (int u = 0; u < 4; u++) {
        int gy = u >> 1, gx = u & 1;
        int c0 = (gy * 2) * 4 + gx * 2;
        float v = fmaxf(fmaxf(v2a[c0], v2a[c0 + 1]), fmaxf(v2a[c0 + 4], v2a[c0 + 5]));
        v1a[u] = v;
        s_up[16 + u][t] = v;
    }
    s_up[20][t] = fmaxf(fmaxf(v1a[0], v1a[1]), fmaxf(v1a[2], v1a[3]));
    __syncthreads();

    // --- phase B: L2 norms per cell ---
    for (int u = w; u < NTOT; u += 8) {
        float acc = 0.f;
        #pragma unroll
        for (int i = 0; i < 8; i++) {
            int ch = lane + 32 * i;
            float v = (u < 64) ? g_pyr[b][u][ch] : s_up[u - 64][ch];
            acc = fmaf(v, v, acc);
        }
        #pragma unroll
        for (int o = 16; o > 0; o >>= 1)
            acc += __shfl_xor_sync(0xffffffffu, acc, o);
        if (lane == 0) sl2[u] = sqrtf(acc);
    }
    __syncthreads();
    if (t < 64) srank3[t] = -1;
    if (t < 16) {
        srank2[t] = -1;
        int gy = t >> 2, gx = t & 3;
        simp2[t] = fabsf(sl2[L2B + t] - sl2[(2 * gy) * 8 + 2 * gx]);
    }
    if (t < 4) {
        srank1[t] = -1;
        int gy = t >> 1, gx = t & 1;
        simp1[t] = fabsf(sl2[L1B + t] - sl2[L2B + (2 * gy) * 4 + 2 * gx]);
    }
    __syncthreads();

    // --- phase C: rank-based top-k (lax.top_k order: desc, ties->lower idx) ---
    if (t < 64) {
        float v = sl2[t];
        int rank = 0;
        #pragma unroll 16
        for (int j = 0; j < 64; j++) {
            float o = sl2[j];
            rank += (o > v) || (o == v && j < t);
        }
        if (rank < 19) {
            srank3[t] = rank;
            ssel[13 + rank] = t;
            int gy = t >> 3, gx = t & 7;
            float* cp = dout + OFS_COORDS + ((size_t)b * ROWS + 13 + rank) * 4;
            cp[0] = (gx + 0.5f) * 0.125f; cp[1] = (gy + 0.5f) * 0.125f;
            cp[2] = 0.125f; cp[3] = 0.125f;
        }
    } else if (t < 80) {
        int n = t - 64;
        float v = simp2[n];
        int rank = 0;
        #pragma unroll
        for (int j = 0; j < 16; j++) {
            float o = simp2[j];
            rank += (o > v) || (o == v && j < n);
        }
        if (rank < 8) {
            srank2[n] = rank;
            ssel[5 + rank] = L2B + n;
            int gy = n >> 2, gx = n & 3;
            float* cp = dout + OFS_COORDS + ((size_t)b * ROWS + 5 + rank) * 4;
            cp[0] = (gx + 0.5f) * 0.25f; cp[1] = (gy + 0.5f) * 0.25f;
            cp[2] = 0.25f; cp[3] = 0.25f;
        }
    } else if (t < 84) {
        int n = t - 80;
        float v = simp1[n];
        int rank = 0;
        #pragma unroll
        for (int j = 0; j < 4; j++) {
            float o = simp1[j];
            rank += (o > v) || (o == v && j < n);
        }
        srank1[n] = rank;
        ssel[1 + rank] = L1B + n;
        int gy = n >> 1, gx = n & 1;
        float* cp = dout + OFS_COORDS + ((size_t)b * ROWS + 1 + rank) * 4;
        cp[0] = (gx + 0.5f) * 0.5f; cp[1] = (gy + 0.5f) * 0.5f;
        cp[2] = 0.5f; cp[3] = 0.5f;
    } else if (t == 84) {
        ssel[0] = L0B;
        float* cp = dout + OFS_COORDS + ((size_t)b * ROWS) * 4;
        cp[0] = 0.5f; cp[1] = 0.5f; cp[2] = 1.0f; cp[3] = 1.0f;
        if (b == 0) dout[OFS_SPARSITY] = 32.0f / 65536.0f;
    }
    __syncthreads();

    // --- phase D: fine-cell -> row map ---
    if (t < 64) {
        int gy = t >> 3, gx = t & 7;
        int row;
        if (srank3[t] >= 0) {
            row = 13 + srank3[t];
        } else {
            int c2 = (gy >> 1) * 4 + (gx >> 1);
            if (srank2[c2] >= 0) row = 5 + srank2[c2];
            else                 row = 1 + srank1[(gy >> 2) * 2 + (gx >> 2)];
        }
        g_map8[b][t] = row;
    }
    __syncthreads();

    // --- phase E: LayerNorm, warp-per-row (4 rows per warp) -> g_kfn ---
    #pragma unroll
    for (int rr = 0; rr < 4; rr++) {
        int row  = w + rr * 8;
        int cell = ssel[row];
        float vals[8];
        #pragma unroll
        for (int i = 0; i < 8; i++) {
            int ch = lane + 32 * i;
            vals[i] = (cell < 64) ? g_pyr[b][cell][ch] : s_up[cell - 64][ch];
        }
        float s = 0.f;
        #pragma unroll
        for (int i = 0; i < 8; i++) s += vals[i];
        #pragma unroll
        for (int o = 16; o > 0; o >>= 1) s += __shfl_xor_sync(0xffffffffu, s, o);
        float mean = s * (1.0f / 256.0f);
        float s2 = 0.f;
        #pragma unroll
        for (int i = 0; i < 8; i++) {
            float d = vals[i] - mean;
            s2 = fmaf(d, d, s2);
        }
        #pragma unroll
        for (int o = 16; o > 0; o >>= 1) s2 += __shfl_xor_sync(0xffffffffu, s2, o);
        float inv = rsqrtf(s2 * (1.0f / 256.0f) + 1e-5f);
        #pragma unroll
        for (int i = 0; i < 8; i++) {
            int ch = lane + 32 * i;
            g_kfn[b][row][ch] = (vals[i] - mean) * inv * ln_g[ch] + ln_b[ch];
        }
    }
}

// ---------------------------------------------------------------------------
// K3: fill + fused projection. Block (b, d, y8-pair): each warp computes the
// two dots for its x-octant (wT loaded directly, uniform per warp -> L1),
// then streams a 64-row slab. s==0 blocks also emit the 32 sparse_seq rows.
// Grid = B*CO*4. One __syncthreads total.
// ---------------------------------------------------------------------------
__global__ void __launch_bounds__(256, 8)
k_fill(const float* __restrict__ bias, float* __restrict__ dout) {
    int s  = blockIdx.x & 3;            // y8-pair: strips 2s, 2s+1
    int d  = (blockIdx.x >> 2) & 255;
    int b  = blockIdx.x >> 10;
    int t  = threadIdx.x;
    int lane = t & 31, wj = t >> 5;

    __shared__ float sval[16];

    float bd = bias[d];

    // wT column values for this warp's channels (uniform row d -> L1 shared)
    float wv[8];
    #pragma unroll
    for (int i = 0; i < 8; i++)
        wv[i] = g_wT[d][lane + 32 * i];

    // two dots: strip 2s cell wj, strip 2s+1 cell wj (rows uniform per warp)
    {
        int row0 = g_map8[b][16 * s + wj];
        int row1 = g_map8[b][16 * s + 8 + wj];
        float a0 = 0.f, a1 = 0.f;
        #pragma unroll
        for (int i = 0; i < 8; i++) {
            int c = lane + 32 * i;
            a0 = fmaf(g_kfn[b][row0][c], wv[i], a0);
            a1 = fmaf(g_kfn[b][row1][c], wv[i], a1);
        }
        #pragma unroll
        for (int o = 16; o > 0; o >>= 1) {
            a0 += __shfl_xor_sync(0xffffffffu, a0, o);
            a1 += __shfl_xor_sync(0xffffffffu, a1, o);
        }
        if (lane == 0) {
            sval[wj]     = a0 + bd;
            sval[8 + wj] = a1 + bd;
        }
    }

    // sparse_seq: s==0 blocks emit all 32 rows for this (b,d)
    if (s == 0) {
        #pragma unroll
        for (int rr = 0; rr < 4; rr++) {
            int row = wj + rr * 8;
            float acc = 0.f;
            #pragma unroll
            for (int i = 0; i < 8; i++) {
                int c = lane + 32 * i;
                acc = fmaf(g_kfn[b][row][c], wv[i], acc);
            }
            #pragma unroll
            for (int o = 16; o > 0; o >>= 1) acc += __shfl_xor_sync(0xffffffffu, acc, o);
            if (lane == 0)
                dout[OFS_SPARSE + ((size_t)(b * 32 + row)) * 256 + d] = acc + bd;
        }
    }
    __syncthreads();

    // stream the 64-row slab (rows 64s .. 64s+63): 4096 float4, 16 per thread
    float4* base = reinterpret_cast<float4*>(
        dout + ((size_t)((b * 256 + d) * 256 + s * 64)) * 256);
    #pragma unroll
    for (int i = 0; i < 16; i++) {
        int ff = t + i * 256;
        float v = sval[((ff >> 11) << 3) + ((ff & 63) >> 3)];
        __stcs(base + ff, make_float4(v, v, v, v));
    }
}

// ---------------------------------------------------------------------------
extern "C" void kernel_launch(void* const* d_in, const int* in_sizes, int n_in,
                              void* d_out, int out_size) {
    const float* x    = (const float*)d_in[0];
    const float* ln_g = (const float*)d_in[1];
    const float* ln_b = (const float*)d_in[2];
    const float* w    = (const float*)d_in[3];
    const float* bias = (const float*)d_in[4];
    float* out = (float*)d_out;
    (void)in_sizes; (void)n_in; (void)out_size;

    k_pool<<<B_ * C_ * 8 + 64, 256>>>(x, w);
    k_prep<<<B_, 256>>>(ln_g, ln_b, out);
    k_fill<<<B_ * CO_ * 4, 256>>>(bias, out);
}